// round 6
// baseline (speedup 1.0000x reference)
#include <cuda_runtime.h>
#include <cuda_fp16.h>
#include <cstdint>

#define NN 50000
#define NE 1600000

// ---------------- scratch (static device globals; no allocs allowed) ----------------
__device__ float  g_bufA[NN * 128];
__device__ __half g_h16[NN * 128];
__device__ __half g_x16[NN * 19];
__device__ float  g_vm[64];
__device__ float  g_vd[64];
__device__ float  g_sc[2];
__device__ float  g_td[NN];
__device__ int    g_rowp[NN + 1];
__device__ int    g_cnt[NN];
__device__ int    g_part[NN];
__device__ int    g_bsum[256];
__device__ int    g_esrc[NE];

// ---------------- small helpers ----------------
__device__ __forceinline__ uint32_t f2tf(float f) {
    uint32_t r;
    asm("cvt.rna.tf32.f32 %0, %1;" : "=r"(r) : "f"(f));
    return r;
}
// paired-k permutation: within each group of 8 k's, store order [0,4,1,5,2,6,3,7]
// so (k, k+4) are adjacent -> fragment loads become one LDS.64.
__device__ __forceinline__ int kperm(int k) {
    return (k & ~7) | (((k & 3) << 1) | ((k >> 2) & 1));
}

// ---------------- CSR build ----------------
__global__ void count_k(const int* __restrict__ dst, int* __restrict__ cnt, int E) {
    int e = blockIdx.x * blockDim.x + threadIdx.x;
    if (e < E) atomicAdd(&cnt[dst[e]], 1);
}

__global__ void block_scan_k(const int* __restrict__ cnt, int* __restrict__ part,
                             int* __restrict__ bsum, int n) {
    __shared__ int wsum[8];
    int t = threadIdx.x;
    int i = blockIdx.x * 256 + t;
    int v = (i < n) ? cnt[i] : 0;
    int lane = t & 31, w = t >> 5;
    int x = v;
#pragma unroll
    for (int o = 1; o < 32; o <<= 1) {
        int y = __shfl_up_sync(0xffffffffu, x, o);
        if (lane >= o) x += y;
    }
    if (lane == 31) wsum[w] = x;
    __syncthreads();
    if (w == 0) {
        int s = (lane < 8) ? wsum[lane] : 0;
#pragma unroll
        for (int o = 1; o < 8; o <<= 1) {
            int y = __shfl_up_sync(0xffffffffu, s, o);
            if (lane >= o) s += y;
        }
        if (lane < 8) wsum[lane] = s;
    }
    __syncthreads();
    if (w > 0) x += wsum[w - 1];
    if (i < n) part[i] = x;
    if (t == 255) bsum[blockIdx.x] = x;
}

__global__ void scan_bsum_k(int* __restrict__ bsum, int nb) {
    __shared__ int wsum[8];
    int t = threadIdx.x;
    int v = (t < nb) ? bsum[t] : 0;
    int lane = t & 31, w = t >> 5;
    int x = v;
#pragma unroll
    for (int o = 1; o < 32; o <<= 1) {
        int y = __shfl_up_sync(0xffffffffu, x, o);
        if (lane >= o) x += y;
    }
    if (lane == 31) wsum[w] = x;
    __syncthreads();
    if (w == 0) {
        int s = (lane < 8) ? wsum[lane] : 0;
#pragma unroll
        for (int o = 1; o < 8; o <<= 1) {
            int y = __shfl_up_sync(0xffffffffu, s, o);
            if (lane >= o) s += y;
        }
        if (lane < 8) wsum[lane] = s;
    }
    __syncthreads();
    if (w > 0) x += wsum[w - 1];
    if (t < nb) bsum[t] = x - v;   // exclusive
}

__global__ void finalize_rowp_k(const int* __restrict__ part, const int* __restrict__ bsum,
                                int* __restrict__ rowp, int n) {
    int i = blockIdx.x * blockDim.x + threadIdx.x;
    if (i == 0) rowp[0] = 0;
    if (i < n) rowp[i + 1] = part[i] + bsum[i >> 8];
}

__global__ void fill_k(const int* __restrict__ src, const int* __restrict__ dst,
                       const int* __restrict__ rowp, int* __restrict__ cursor,
                       int* __restrict__ esrc, int E) {
    int e = blockIdx.x * blockDim.x + threadIdx.x;
    if (e >= E) return;
    int d = dst[e];
    int p = atomicAdd(&cursor[d], 1);
    esrc[rowp[d] + p] = src[e];
}

// ---------------- fp32 -> fp16 conversion ----------------
__global__ void f2h_k(const float* __restrict__ x, __half* __restrict__ xh, int n) {
    int i = blockIdx.x * blockDim.x + threadIdx.x;
    if (i < n) xh[i] = __float2half_rn(x[i]);
}

// ---------------- head precompute: v_m = W2@m_w, v_d = W2@d_w1 ----------------
__global__ void precomp_k(const float* __restrict__ W2, const float* __restrict__ b2,
                          const float* __restrict__ m_w, const float* __restrict__ m_b,
                          const float* __restrict__ d_w1,
                          float* __restrict__ vm, float* __restrict__ vd,
                          float* __restrict__ sc) {
    int i = threadIdx.x;  // 64 threads
    float am = 0.0f, ad = 0.0f;
    for (int k = 0; k < 64; ++k) {
        float w = W2[i * 64 + k];
        am += w * m_w[k];
        ad += w * d_w1[k];
    }
    vm[i] = am;
    vd[i] = ad;
    if (i == 0) {
        float sm = m_b[0], sd = 0.0f;
        for (int k = 0; k < 64; ++k) {
            sm += b2[k] * m_w[k];
            sd += b2[k] * d_w1[k];
        }
        sc[0] = sm;
        sc[1] = sd;
    }
}

// ---------------- aggregation kernels ----------------
__global__ void agg19h_k(const __half* __restrict__ xh, const int* __restrict__ rowp,
                         const int* __restrict__ esrc, float* __restrict__ z, int n) {
    int w = (blockIdx.x * blockDim.x + threadIdx.x) >> 5;
    int lane = threadIdx.x & 31;
    if (w >= n || lane >= 19) return;
    float acc = __half2float(xh[w * 19 + lane]);
    int s = rowp[w], e = rowp[w + 1];
    int j = s;
    for (; j + 4 <= e; j += 4) {
        int s0 = esrc[j], s1 = esrc[j + 1], s2 = esrc[j + 2], s3 = esrc[j + 3];
        float a = __half2float(xh[s0 * 19 + lane]);
        float b = __half2float(xh[s1 * 19 + lane]);
        float c = __half2float(xh[s2 * 19 + lane]);
        float d = __half2float(xh[s3 * 19 + lane]);
        acc += a; acc += b; acc += c; acc += d;
    }
    for (; j < e; ++j) acc += __half2float(xh[esrc[j] * 19 + lane]);
    z[w * 19 + lane] = acc;
}

__device__ __forceinline__ void acc_h4(float4& acc, uint2 v) {
    float2 f0 = __half22float2(*(__half2*)&v.x);
    float2 f1 = __half22float2(*(__half2*)&v.y);
    acc.x += f0.x; acc.y += f0.y; acc.z += f1.x; acc.w += f1.y;
}

__global__ void agg128h_k(const __half* __restrict__ h, const int* __restrict__ rowp,
                          const int* __restrict__ esrc, float* __restrict__ z, int n) {
    int w = (blockIdx.x * blockDim.x + threadIdx.x) >> 5;
    int lane = threadIdx.x & 31;
    if (w >= n) return;
    const uint2* h4 = (const uint2*)h;   // 4 halfs per uint2, 32 per row
    float4 acc = make_float4(0.f, 0.f, 0.f, 0.f);
    acc_h4(acc, h4[w * 32 + lane]);
    int s = rowp[w], e = rowp[w + 1];
    int j = s;
    for (; j + 4 <= e; j += 4) {
        int s0 = esrc[j], s1 = esrc[j + 1], s2 = esrc[j + 2], s3 = esrc[j + 3];
        uint2 a = h4[s0 * 32 + lane];
        uint2 b = h4[s1 * 32 + lane];
        uint2 c = h4[s2 * 32 + lane];
        uint2 d = h4[s3 * 32 + lane];
        acc_h4(acc, a); acc_h4(acc, b); acc_h4(acc, c); acc_h4(acc, d);
    }
    for (; j < e; ++j) acc_h4(acc, h4[esrc[j] * 32 + lane]);
    ((float4*)z)[w * 32 + lane] = acc;
}

// 64-dim fp16 gather + bias + ReLU + fused dual head dot products.
__global__ void agg64_heads_k(const __half* __restrict__ y, const int* __restrict__ rowp,
                              const int* __restrict__ esrc, const float* __restrict__ bias,
                              const float* __restrict__ vm, const float* __restrict__ vd,
                              const float* __restrict__ sc,
                              float* __restrict__ mmse_out, float* __restrict__ td, int n) {
    int w = (blockIdx.x * blockDim.x + threadIdx.x) >> 5;
    int lane = threadIdx.x & 31;
    if (w >= n) return;
    const __half2* h2 = (const __half2*)y;  // 32 half2 per row
    float2 acc = __half22float2(h2[w * 32 + lane]);
    int s = rowp[w], e = rowp[w + 1];
    int j = s;
    for (; j + 4 <= e; j += 4) {
        int s0 = esrc[j], s1 = esrc[j + 1], s2 = esrc[j + 2], s3 = esrc[j + 3];
        float2 a = __half22float2(h2[s0 * 32 + lane]);
        float2 b = __half22float2(h2[s1 * 32 + lane]);
        float2 c = __half22float2(h2[s2 * 32 + lane]);
        float2 d = __half22float2(h2[s3 * 32 + lane]);
        acc.x += a.x; acc.y += a.y; acc.x += b.x; acc.y += b.y;
        acc.x += c.x; acc.y += c.y; acc.x += d.x; acc.y += d.y;
    }
    for (; j < e; ++j) {
        float2 f = __half22float2(h2[esrc[j] * 32 + lane]);
        acc.x += f.x; acc.y += f.y;
    }
    float ux = fmaxf(acc.x + bias[lane * 2], 0.0f);
    float uy = fmaxf(acc.y + bias[lane * 2 + 1], 0.0f);
    float dm = ux * vm[lane * 2] + uy * vm[lane * 2 + 1];
    float dd = ux * vd[lane * 2] + uy * vd[lane * 2 + 1];
#pragma unroll
    for (int o = 16; o; o >>= 1) {
        dm += __shfl_down_sync(0xffffffffu, dm, o);
        dd += __shfl_down_sync(0xffffffffu, dd, o);
    }
    if (lane == 0) {
        float m = dm + sc[0];
        mmse_out[w] = (m > 0.0f) ? m : 0.01f * m;
        td[w] = dd + sc[1];
    }
}

__global__ void discrim_k(const float* __restrict__ td, const int* __restrict__ rowp,
                          const int* __restrict__ esrc, const float* __restrict__ d_b1,
                          const float* __restrict__ d_w2, const float* __restrict__ d_b2,
                          float* __restrict__ out, int n) {
    int i = blockIdx.x * blockDim.x + threadIdx.x;
    if (i >= n) return;
    float acc = td[i];
    int s = rowp[i], e = rowp[i + 1];
    int j = s;
    for (; j + 4 <= e; j += 4) {
        float a = td[esrc[j]], b = td[esrc[j + 1]];
        float c = td[esrc[j + 2]], d = td[esrc[j + 3]];
        acc += a; acc += b; acc += c; acc += d;
    }
    for (; j < e; ++j) acc += td[esrc[j]];
    float u = acc + d_b1[0];
    u = fmaxf(u, 0.0f);
    out[i] = u * d_w2[0] + d_b2[0];
}

// ---------------- fused tf32 MLP kernels ----------------
// Per-warp MMA over full K: rows rbase..rbase+31 (2 x m16), cols cbase..cbase+NT*8-1.
// As/Ws are in the paired-k layout; fragment loads are LDS.64 (uint2).
template <int KP, int NT>
__device__ __forceinline__ void mma_phase(const uint32_t* __restrict__ As,
                                          const uint32_t* __restrict__ Ws,
                                          int rbase, int cbase, int g, int t4,
                                          float (&acc)[2][NT][4]) {
    constexpr int STR = KP + 4;
#pragma unroll
    for (int mt = 0; mt < 2; ++mt)
#pragma unroll
        for (int nt = 0; nt < NT; ++nt)
#pragma unroll
            for (int q = 0; q < 4; ++q) acc[mt][nt][q] = 0.0f;

#pragma unroll
    for (int k0 = 0; k0 < KP; k0 += 8) {
        uint32_t a[2][4];
#pragma unroll
        for (int mt = 0; mt < 2; ++mt) {
            int r = rbase + mt * 16 + g;
            uint2 p0 = *(const uint2*)(As + r * STR + k0 + t4 * 2);
            uint2 p1 = *(const uint2*)(As + (r + 8) * STR + k0 + t4 * 2);
            a[mt][0] = p0.x; a[mt][1] = p1.x; a[mt][2] = p0.y; a[mt][3] = p1.y;
        }
        uint32_t b[NT][2];
#pragma unroll
        for (int nt = 0; nt < NT; ++nt) {
            uint2 bb = *(const uint2*)(Ws + (cbase + nt * 8 + g) * STR + k0 + t4 * 2);
            b[nt][0] = bb.x; b[nt][1] = bb.y;
        }
#pragma unroll
        for (int mt = 0; mt < 2; ++mt)
#pragma unroll
            for (int nt = 0; nt < NT; ++nt) {
                asm volatile(
                    "mma.sync.aligned.m16n8k8.row.col.f32.tf32.tf32.f32 "
                    "{%0,%1,%2,%3}, {%4,%5,%6,%7}, {%8,%9}, {%0,%1,%2,%3};\n"
                    : "+f"(acc[mt][nt][0]), "+f"(acc[mt][nt][1]),
                      "+f"(acc[mt][nt][2]), "+f"(acc[mt][nt][3])
                    : "r"(a[mt][0]), "r"(a[mt][1]), "r"(a[mt][2]), "r"(a[mt][3]),
                      "r"(b[nt][0]), "r"(b[nt][1]));
            }
    }
}

// Write relu(acc + bias) back into As (stride 132) in paired-k tf32 layout.
template <int NT>
__device__ __forceinline__ void write_u(uint32_t* __restrict__ As, const float* __restrict__ Bs,
                                        float (&acc)[2][NT][4],
                                        int rbase, int cbase, int g, int t4) {
#pragma unroll
    for (int mt = 0; mt < 2; ++mt) {
        int r1 = rbase + mt * 16 + g, r2 = r1 + 8;
#pragma unroll
        for (int nt = 0; nt < NT; ++nt) {
            int c0 = cbase + nt * 8 + t4 * 2, c1 = c0 + 1;
            float b0 = Bs[c0], b1 = Bs[c1];
            As[r1 * 132 + kperm(c0)] = f2tf(fmaxf(acc[mt][nt][0] + b0, 0.0f));
            As[r1 * 132 + kperm(c1)] = f2tf(fmaxf(acc[mt][nt][1] + b1, 0.0f));
            As[r2 * 132 + kperm(c0)] = f2tf(fmaxf(acc[mt][nt][2] + b0, 0.0f));
            As[r2 * 132 + kperm(c1)] = f2tf(fmaxf(acc[mt][nt][3] + b1, 0.0f));
        }
    }
}

// Stage W[IN][OUT] transposed into Ws[col][kperm(k)] (tf32).
template <int IN, int OUT>
__device__ __forceinline__ void stage_w(const float* __restrict__ W, uint32_t* __restrict__ Ws,
                                        int tid) {
    constexpr int KP = ((IN + 7) / 8) * 8;
    constexpr int STR = KP + 4;
    for (int i = tid; i < IN * OUT; i += 256) {
        int k = i / OUT, col = i - k * OUT;
        Ws[col * STR + kperm(k)] = f2tf(W[i]);
    }
    if (KP > IN) {
        for (int i = tid; i < (KP - IN) * OUT; i += 256) {
            int col = i % OUT, k = IN + i / OUT;
            Ws[col * STR + kperm(k)] = 0u;
        }
    }
}

// fused2: h_out16 = relu( relu(A@W1+b1) @ W2 + b2 ), TM=128 rows/block, OUT=128.
template <int IN>
__global__ void fused2_k(const float* __restrict__ A,
                         const float* __restrict__ W1, const float* __restrict__ B1,
                         const float* __restrict__ W2, const float* __restrict__ B2,
                         __half* __restrict__ Ch, int n) {
    constexpr int KP1 = ((IN + 7) / 8) * 8;
    constexpr int STR1 = KP1 + 4;
    constexpr int W1SZ = 128 * STR1;
    constexpr int W2SZ = 128 * 132;
    constexpr int ASZ = 128 * 132;

    extern __shared__ uint32_t smu[];
    uint32_t* Ws1 = smu;
    uint32_t* Ws2 = smu + W1SZ;
    uint32_t* As  = smu + W1SZ + W2SZ;
    float* Bs1 = (float*)(smu + W1SZ + W2SZ + ASZ);
    float* Bs2 = Bs1 + 128;

    int tid = threadIdx.x;
    int row0 = blockIdx.x * 128;

    stage_w<IN, 128>(W1, Ws1, tid);
    stage_w<128, 128>(W2, Ws2, tid);
    for (int i = tid; i < 128; i += 256) { Bs1[i] = B1[i]; Bs2[i] = B2[i]; }

    for (int i = tid; i < 128 * IN; i += 256) {
        int r = i / IN, k = i - r * IN;
        int row = row0 + r;
        As[r * STR1 + kperm(k)] = (row < n) ? f2tf(A[(size_t)row * IN + k]) : 0u;
    }
    if (KP1 > IN) {
        for (int i = tid; i < 128 * (KP1 - IN); i += 256) {
            int r = i / (KP1 - IN), k = IN + i % (KP1 - IN);
            As[r * STR1 + kperm(k)] = 0u;
        }
    }
    __syncthreads();

    int w = tid >> 5, lane = tid & 31;
    int wm = w >> 1, wn = w & 1;   // 4x2 warp grid: 32 rows x 64 cols per warp
    int g = lane >> 2, t4 = lane & 3;
    int rbase = wm * 32, cbase = wn * 64;

    float acc[2][8][4];
    mma_phase<KP1, 8>(As, Ws1, rbase, cbase, g, t4, acc);
    __syncthreads();                                   // reads of z done
    write_u<8>(As, Bs1, acc, rbase, cbase, g, t4);     // u = relu(z@W1+b1)
    __syncthreads();
    mma_phase<128, 8>(As, Ws2, rbase, cbase, g, t4, acc);

    // epilogue: h = relu(u@W2 + b2) -> fp16
#pragma unroll
    for (int mt = 0; mt < 2; ++mt) {
        int r1 = row0 + rbase + mt * 16 + g;
#pragma unroll
        for (int nt = 0; nt < 8; ++nt) {
            int col = cbase + nt * 8 + t4 * 2;
            float b0 = Bs2[col], b1 = Bs2[col + 1];
            if (r1 < n) {
                float v0 = fmaxf(acc[mt][nt][0] + b0, 0.0f);
                float v1 = fmaxf(acc[mt][nt][1] + b1, 0.0f);
                *(__half2*)(Ch + (size_t)r1 * 128 + col) = __floats2half2_rn(v0, v1);
            }
            if (r1 + 8 < n) {
                float v2 = fmaxf(acc[mt][nt][2] + b0, 0.0f);
                float v3 = fmaxf(acc[mt][nt][3] + b1, 0.0f);
                *(__half2*)(Ch + (size_t)(r1 + 8) * 128 + col) = __floats2half2_rn(v2, v3);
            }
        }
    }
}

// fused3: y16 = relu( relu(A@W1+b1) @ W2 + b2 ) @ W3, TM=64 rows/block.
// W1,W2: 128x128; W3: 128x64. Output y is 64-dim fp16.
__global__ void fused3_k(const float* __restrict__ A,
                         const float* __restrict__ W1, const float* __restrict__ B1,
                         const float* __restrict__ W2, const float* __restrict__ B2,
                         const float* __restrict__ W3,
                         __half* __restrict__ Ch, int n) {
    constexpr int W1SZ = 128 * 132;
    constexpr int W2SZ = 128 * 132;
    constexpr int W3SZ = 64 * 132;
    constexpr int ASZ = 64 * 132;

    extern __shared__ uint32_t smu[];
    uint32_t* Ws1 = smu;
    uint32_t* Ws2 = smu + W1SZ;
    uint32_t* Ws3 = smu + W1SZ + W2SZ;
    uint32_t* As  = smu + W1SZ + W2SZ + W3SZ;
    float* Bs1 = (float*)(smu + W1SZ + W2SZ + W3SZ + ASZ);
    float* Bs2 = Bs1 + 128;

    int tid = threadIdx.x;
    int row0 = blockIdx.x * 64;

    stage_w<128, 128>(W1, Ws1, tid);
    stage_w<128, 128>(W2, Ws2, tid);
    stage_w<128, 64>(W3, Ws3, tid);
    for (int i = tid; i < 128; i += 256) { Bs1[i] = B1[i]; Bs2[i] = B2[i]; }

    for (int i = tid; i < 64 * 128; i += 256) {
        int r = i >> 7, k = i & 127;
        int row = row0 + r;
        As[r * 132 + kperm(k)] = (row < n) ? f2tf(A[(size_t)row * 128 + k]) : 0u;
    }
    __syncthreads();

    int w = tid >> 5, lane = tid & 31;
    int wm = w >> 2, wn = w & 3;   // 2x4 warp grid: 32 rows x 32 cols per warp
    int g = lane >> 2, t4 = lane & 3;
    int rbase = wm * 32;

    {
        float acc[2][4][4];
        mma_phase<128, 4>(As, Ws1, rbase, wn * 32, g, t4, acc);
        __syncthreads();
        write_u<4>(As, Bs1, acc, rbase, wn * 32, g, t4);
        __syncthreads();
        mma_phase<128, 4>(As, Ws2, rbase, wn * 32, g, t4, acc);
        __syncthreads();
        write_u<4>(As, Bs2, acc, rbase, wn * 32, g, t4);
        __syncthreads();
    }

    // phase 3: y = h2 @ W3 (no bias, no relu), OUT=64 -> 16 cols per warp
    float acc3[2][2][4];
    mma_phase<128, 2>(As, Ws3, rbase, wn * 16, g, t4, acc3);

#pragma unroll
    for (int mt = 0; mt < 2; ++mt) {
        int r1 = row0 + rbase + mt * 16 + g;
#pragma unroll
        for (int nt = 0; nt < 2; ++nt) {
            int col = wn * 16 + nt * 8 + t4 * 2;
            if (r1 < n)
                *(__half2*)(Ch + (size_t)r1 * 64 + col) =
                    __floats2half2_rn(acc3[mt][nt][0], acc3[mt][nt][1]);
            if (r1 + 8 < n)
                *(__half2*)(Ch + (size_t)(r1 + 8) * 64 + col) =
                    __floats2half2_rn(acc3[mt][nt][2], acc3[mt][nt][3]);
        }
    }
}

// ---------------- host ----------------
extern "C" void kernel_launch(void* const* d_in, const int* in_sizes, int n_in,
                              void* d_out, int out_size) {
    const float* x   = (const float*)d_in[0];
    const int*   ei  = (const int*)d_in[1];
    const int E = in_sizes[1] / 2;
    const int n = in_sizes[0] / 19;
    const int* src = ei;
    const int* dst = ei + E;

    const float* l0w1 = (const float*)d_in[2];
    const float* l0b1 = (const float*)d_in[3];
    const float* l0w2 = (const float*)d_in[4];
    const float* l0b2 = (const float*)d_in[5];
    const float* l1w1 = (const float*)d_in[6];
    const float* l1b1 = (const float*)d_in[7];
    const float* l1w2 = (const float*)d_in[8];
    const float* l1b2 = (const float*)d_in[9];
    const float* l2w1 = (const float*)d_in[10];
    const float* l2b1 = (const float*)d_in[11];
    const float* l2w2 = (const float*)d_in[12];
    const float* l2b2 = (const float*)d_in[13];
    const float* l3w1 = (const float*)d_in[14];
    const float* l3b1 = (const float*)d_in[15];
    const float* l3w2 = (const float*)d_in[16];
    const float* l3b2 = (const float*)d_in[17];
    const float* m_w  = (const float*)d_in[18];
    const float* m_b  = (const float*)d_in[19];
    const float* d_w1 = (const float*)d_in[20];
    const float* d_b1 = (const float*)d_in[21];
    const float* d_w2 = (const float*)d_in[22];
    const float* d_b2 = (const float*)d_in[23];

    void *pA, *pH, *pX, *pVm, *pVd, *pSc, *pTd, *pRow, *pCnt, *pPart, *pBsum, *pEsrc;
    cudaGetSymbolAddress(&pA, g_bufA);
    cudaGetSymbolAddress(&pH, g_h16);
    cudaGetSymbolAddress(&pX, g_x16);
    cudaGetSymbolAddress(&pVm, g_vm);
    cudaGetSymbolAddress(&pVd, g_vd);
    cudaGetSymbolAddress(&pSc, g_sc);
    cudaGetSymbolAddress(&pTd, g_td);
    cudaGetSymbolAddress(&pRow, g_rowp);
    cudaGetSymbolAddress(&pCnt, g_cnt);
    cudaGetSymbolAddress(&pPart, g_part);
    cudaGetSymbolAddress(&pBsum, g_bsum);
    cudaGetSymbolAddress(&pEsrc, g_esrc);
    float*  bufA = (float*)pA;
    __half* h16  = (__half*)pH;
    __half* x16  = (__half*)pX;
    float*  vm   = (float*)pVm;
    float*  vd   = (float*)pVd;
    float*  sc   = (float*)pSc;
    float*  td   = (float*)pTd;
    int* rowp = (int*)pRow;
    int* cnt  = (int*)pCnt;
    int* part = (int*)pPart;
    int* bsum = (int*)pBsum;
    int* esrc = (int*)pEsrc;

    float* out = (float*)d_out;

    const int TB = 256;
    const int edgeBlocks = (E + TB - 1) / TB;
    const int nodeBlocks = (n + TB - 1) / TB;
    const int warpBlocks = (n * 32 + TB - 1) / TB;  // warp per node
    const int nb = (n + 255) / 256;

    // fused kernel smem sizes
    const size_t sm_f2_19  = (size_t)(128 * 28 + 128 * 132 + 128 * 132) * 4 + 256 * 4;
    const size_t sm_f2_128 = (size_t)(128 * 132 * 3) * 4 + 256 * 4;
    const size_t sm_f3     = (size_t)(128 * 132 * 2 + 64 * 132 * 2) * 4 + 256 * 4;
    cudaFuncSetAttribute(fused2_k<19>, cudaFuncAttributeMaxDynamicSharedMemorySize, (int)sm_f2_19);
    cudaFuncSetAttribute(fused2_k<128>, cudaFuncAttributeMaxDynamicSharedMemorySize, (int)sm_f2_128);
    cudaFuncSetAttribute(fused3_k, cudaFuncAttributeMaxDynamicSharedMemorySize, (int)sm_f3);

    // ---- independent precomputes ----
    f2h_k<<<(n * 19 + 255) / 256, 256>>>(x, x16, n * 19);
    precomp_k<<<1, 64>>>(l3w2, l3b2, m_w, m_b, d_w1, vm, vd, sc);

    // ---- CSR build ----
    cudaMemsetAsync(cnt, 0, (size_t)n * sizeof(int));
    count_k<<<edgeBlocks, TB>>>(dst, cnt, E);
    block_scan_k<<<nb, 256>>>(cnt, part, bsum, n);
    scan_bsum_k<<<1, 256>>>(bsum, nb);
    finalize_rowp_k<<<nodeBlocks, TB>>>(part, bsum, rowp, n);
    cudaMemsetAsync(cnt, 0, (size_t)n * sizeof(int));
    fill_k<<<edgeBlocks, TB>>>(src, dst, rowp, cnt, esrc, E);

    const int fb128 = (n + 127) / 128;
    const int fb64  = (n + 63) / 64;

    // ---- layer 0: agg19 -> fused MLP -> h0 fp16 ----
    agg19h_k<<<warpBlocks, TB>>>(x16, rowp, esrc, bufA, n);
    fused2_k<19><<<fb128, 256, sm_f2_19>>>(bufA, l0w1, l0b1, l0w2, l0b2, h16, n);

    // ---- layer 1 ----
    agg128h_k<<<warpBlocks, TB>>>(h16, rowp, esrc, bufA, n);
    fused2_k<128><<<fb128, 256, sm_f2_128>>>(bufA, l1w1, l1b1, l1w2, l1b2, h16, n);

    // ---- layer 2 (+ layer-3 GEMM1 fused): y = relu(mlp(z2)) @ W13, fp16 64-dim ----
    agg128h_k<<<warpBlocks, TB>>>(h16, rowp, esrc, bufA, n);
    fused3_k<<<fb64, 256, sm_f3>>>(bufA, l2w1, l2b1, l2w2, l2b2, l3w1, h16, n);

    // ---- layer 3 agg (64-dim) + fused heads ----
    agg64_heads_k<<<warpBlocks, TB>>>(h16, rowp, esrc, l3b1, vm, vd, sc,
                                      out + n, td, n);

    // ---- discriminator ----
    discrim_k<<<nodeBlocks, TB>>>(td, rowp, esrc, d_b1, d_w2, d_b2, out, n);
}

// round 7
// speedup vs baseline: 1.1826x; 1.1826x over previous
#include <cuda_runtime.h>
#include <cuda_fp16.h>
#include <cstdint>

#define NN 50000
#define NE 1600000

// ---------------- scratch (static device globals; no allocs allowed) ----------------
__device__ __half g_h16[NN * 128];   // gather source / y
__device__ __half g_z16[NN * 128];   // agg output / GEMM input
__device__ __half g_t16[NN * 128];   // MLP intermediate
__device__ __half g_x16[NN * 19];
__device__ float  g_vm[64];
__device__ float  g_vd[64];
__device__ float  g_sc[2];
__device__ float  g_td[NN];
__device__ int    g_rowp[NN + 1];
__device__ int    g_cnt[NN];
__device__ int    g_part[NN];
__device__ int    g_bsum[256];
__device__ int    g_esrc[NE];

// ---------------- CSR build ----------------
__global__ void count_k(const int* __restrict__ dst, int* __restrict__ cnt, int E) {
    int e = blockIdx.x * blockDim.x + threadIdx.x;
    if (e < E) atomicAdd(&cnt[dst[e]], 1);
}

__global__ void block_scan_k(const int* __restrict__ cnt, int* __restrict__ part,
                             int* __restrict__ bsum, int n) {
    __shared__ int wsum[8];
    int t = threadIdx.x;
    int i = blockIdx.x * 256 + t;
    int v = (i < n) ? cnt[i] : 0;
    int lane = t & 31, w = t >> 5;
    int x = v;
#pragma unroll
    for (int o = 1; o < 32; o <<= 1) {
        int y = __shfl_up_sync(0xffffffffu, x, o);
        if (lane >= o) x += y;
    }
    if (lane == 31) wsum[w] = x;
    __syncthreads();
    if (w == 0) {
        int s = (lane < 8) ? wsum[lane] : 0;
#pragma unroll
        for (int o = 1; o < 8; o <<= 1) {
            int y = __shfl_up_sync(0xffffffffu, s, o);
            if (lane >= o) s += y;
        }
        if (lane < 8) wsum[lane] = s;
    }
    __syncthreads();
    if (w > 0) x += wsum[w - 1];
    if (i < n) part[i] = x;
    if (t == 255) bsum[blockIdx.x] = x;
}

__global__ void scan_bsum_k(int* __restrict__ bsum, int nb) {
    __shared__ int wsum[8];
    int t = threadIdx.x;
    int v = (t < nb) ? bsum[t] : 0;
    int lane = t & 31, w = t >> 5;
    int x = v;
#pragma unroll
    for (int o = 1; o < 32; o <<= 1) {
        int y = __shfl_up_sync(0xffffffffu, x, o);
        if (lane >= o) x += y;
    }
    if (lane == 31) wsum[w] = x;
    __syncthreads();
    if (w == 0) {
        int s = (lane < 8) ? wsum[lane] : 0;
#pragma unroll
        for (int o = 1; o < 8; o <<= 1) {
            int y = __shfl_up_sync(0xffffffffu, s, o);
            if (lane >= o) s += y;
        }
        if (lane < 8) wsum[lane] = s;
    }
    __syncthreads();
    if (w > 0) x += wsum[w - 1];
    if (t < nb) bsum[t] = x - v;   // exclusive
}

__global__ void finalize_rowp_k(const int* __restrict__ part, const int* __restrict__ bsum,
                                int* __restrict__ rowp, int n) {
    int i = blockIdx.x * blockDim.x + threadIdx.x;
    if (i == 0) rowp[0] = 0;
    if (i < n) rowp[i + 1] = part[i] + bsum[i >> 8];
}

__global__ void fill_k(const int* __restrict__ src, const int* __restrict__ dst,
                       const int* __restrict__ rowp, int* __restrict__ cursor,
                       int* __restrict__ esrc, int E) {
    int e = blockIdx.x * blockDim.x + threadIdx.x;
    if (e >= E) return;
    int d = dst[e];
    int p = atomicAdd(&cursor[d], 1);
    esrc[rowp[d] + p] = src[e];
}

// ---------------- fp32 -> fp16 conversion ----------------
__global__ void f2h_k(const float* __restrict__ x, __half* __restrict__ xh, int n) {
    int i = blockIdx.x * blockDim.x + threadIdx.x;
    if (i < n) xh[i] = __float2half_rn(x[i]);
}

// ---------------- head precompute: v_m = W2@m_w, v_d = W2@d_w1 ----------------
__global__ void precomp_k(const float* __restrict__ W2, const float* __restrict__ b2,
                          const float* __restrict__ m_w, const float* __restrict__ m_b,
                          const float* __restrict__ d_w1,
                          float* __restrict__ vm, float* __restrict__ vd,
                          float* __restrict__ sc) {
    int i = threadIdx.x;  // 64 threads
    float am = 0.0f, ad = 0.0f;
    for (int k = 0; k < 64; ++k) {
        float w = W2[i * 64 + k];
        am += w * m_w[k];
        ad += w * d_w1[k];
    }
    vm[i] = am;
    vd[i] = ad;
    if (i == 0) {
        float sm = m_b[0], sd = 0.0f;
        for (int k = 0; k < 64; ++k) {
            sm += b2[k] * m_w[k];
            sd += b2[k] * d_w1[k];
        }
        sc[0] = sm;
        sc[1] = sd;
    }
}

// ---------------- aggregation kernels (warp per node; z = self + sum_{j->i}) ----------------
__global__ void agg19h_k(const __half* __restrict__ xh, const int* __restrict__ rowp,
                         const int* __restrict__ esrc, __half* __restrict__ z, int n) {
    int w = (blockIdx.x * blockDim.x + threadIdx.x) >> 5;
    int lane = threadIdx.x & 31;
    if (w >= n || lane >= 19) return;
    float acc = __half2float(xh[w * 19 + lane]);
    int s = rowp[w], e = rowp[w + 1];
    int j = s;
    for (; j + 4 <= e; j += 4) {
        int s0 = esrc[j], s1 = esrc[j + 1], s2 = esrc[j + 2], s3 = esrc[j + 3];
        float a = __half2float(xh[s0 * 19 + lane]);
        float b = __half2float(xh[s1 * 19 + lane]);
        float c = __half2float(xh[s2 * 19 + lane]);
        float d = __half2float(xh[s3 * 19 + lane]);
        acc += a; acc += b; acc += c; acc += d;
    }
    for (; j < e; ++j) acc += __half2float(xh[esrc[j] * 19 + lane]);
    z[w * 19 + lane] = __float2half_rn(acc);
}

__device__ __forceinline__ void acc_h4(float4& acc, uint2 v) {
    float2 f0 = __half22float2(*(__half2*)&v.x);
    float2 f1 = __half22float2(*(__half2*)&v.y);
    acc.x += f0.x; acc.y += f0.y; acc.z += f1.x; acc.w += f1.y;
}

// 128-dim fp16 gather -> fp16 z out. Each lane covers 4 features (uint2 = 8B).
__global__ void agg128h_k(const __half* __restrict__ h, const int* __restrict__ rowp,
                          const int* __restrict__ esrc, __half* __restrict__ z, int n) {
    int w = (blockIdx.x * blockDim.x + threadIdx.x) >> 5;
    int lane = threadIdx.x & 31;
    if (w >= n) return;
    const uint2* h4 = (const uint2*)h;
    float4 acc = make_float4(0.f, 0.f, 0.f, 0.f);
    acc_h4(acc, h4[w * 32 + lane]);
    int s = rowp[w], e = rowp[w + 1];
    int j = s;
    for (; j + 4 <= e; j += 4) {
        int s0 = esrc[j], s1 = esrc[j + 1], s2 = esrc[j + 2], s3 = esrc[j + 3];
        uint2 a = h4[s0 * 32 + lane];
        uint2 b = h4[s1 * 32 + lane];
        uint2 c = h4[s2 * 32 + lane];
        uint2 d = h4[s3 * 32 + lane];
        acc_h4(acc, a); acc_h4(acc, b); acc_h4(acc, c); acc_h4(acc, d);
    }
    for (; j < e; ++j) acc_h4(acc, h4[esrc[j] * 32 + lane]);
    uint2 o;
    *(__half2*)&o.x = __floats2half2_rn(acc.x, acc.y);
    *(__half2*)&o.y = __floats2half2_rn(acc.z, acc.w);
    ((uint2*)z)[w * 32 + lane] = o;
}

// 64-dim fp16 gather + bias + ReLU + fused dual head dot products.
__global__ void agg64_heads_k(const __half* __restrict__ y, const int* __restrict__ rowp,
                              const int* __restrict__ esrc, const float* __restrict__ bias,
                              const float* __restrict__ vm, const float* __restrict__ vd,
                              const float* __restrict__ sc,
                              float* __restrict__ mmse_out, float* __restrict__ td, int n) {
    int w = (blockIdx.x * blockDim.x + threadIdx.x) >> 5;
    int lane = threadIdx.x & 31;
    if (w >= n) return;
    const __half2* h2 = (const __half2*)y;  // 32 half2 per row
    float2 acc = __half22float2(h2[w * 32 + lane]);
    int s = rowp[w], e = rowp[w + 1];
    int j = s;
    for (; j + 4 <= e; j += 4) {
        int s0 = esrc[j], s1 = esrc[j + 1], s2 = esrc[j + 2], s3 = esrc[j + 3];
        float2 a = __half22float2(h2[s0 * 32 + lane]);
        float2 b = __half22float2(h2[s1 * 32 + lane]);
        float2 c = __half22float2(h2[s2 * 32 + lane]);
        float2 d = __half22float2(h2[s3 * 32 + lane]);
        acc.x += a.x; acc.y += a.y; acc.x += b.x; acc.y += b.y;
        acc.x += c.x; acc.y += c.y; acc.x += d.x; acc.y += d.y;
    }
    for (; j < e; ++j) {
        float2 f = __half22float2(h2[esrc[j] * 32 + lane]);
        acc.x += f.x; acc.y += f.y;
    }
    float ux = fmaxf(acc.x + bias[lane * 2], 0.0f);
    float uy = fmaxf(acc.y + bias[lane * 2 + 1], 0.0f);
    float dm = ux * vm[lane * 2] + uy * vm[lane * 2 + 1];
    float dd = ux * vd[lane * 2] + uy * vd[lane * 2 + 1];
#pragma unroll
    for (int o = 16; o; o >>= 1) {
        dm += __shfl_down_sync(0xffffffffu, dm, o);
        dd += __shfl_down_sync(0xffffffffu, dd, o);
    }
    if (lane == 0) {
        float m = dm + sc[0];
        mmse_out[w] = (m > 0.0f) ? m : 0.01f * m;
        td[w] = dd + sc[1];
    }
}

__global__ void discrim_k(const float* __restrict__ td, const int* __restrict__ rowp,
                          const int* __restrict__ esrc, const float* __restrict__ d_b1,
                          const float* __restrict__ d_w2, const float* __restrict__ d_b2,
                          float* __restrict__ out, int n) {
    int i = blockIdx.x * blockDim.x + threadIdx.x;
    if (i >= n) return;
    float acc = td[i];
    int s = rowp[i], e = rowp[i + 1];
    int j = s;
    for (; j + 4 <= e; j += 4) {
        float a = td[esrc[j]], b = td[esrc[j + 1]];
        float c = td[esrc[j + 2]], d = td[esrc[j + 3]];
        acc += a; acc += b; acc += c; acc += d;
    }
    for (; j < e; ++j) acc += td[esrc[j]];
    float u = acc + d_b1[0];
    u = fmaxf(u, 0.0f);
    out[i] = u * d_w2[0] + d_b2[0];
}

// ---------------- fp16 tensor-core GEMM (m16n8k16, fp32 accumulate) ----------------
// C[n,OUT] = act(A[n,IN] @ W[IN,OUT] + bias); A fp16, W fp32->fp16, C fp16.
// Block 256 threads (warps as 2m x 4n), 64-row tile, K fully resident.
template <int IN, int OUT, bool RELU>
__global__ void gemm_h_k(const __half* __restrict__ A, const float* __restrict__ W,
                         const float* __restrict__ bias, __half* __restrict__ C, int n) {
    constexpr int KP = ((IN + 15) / 16) * 16;   // 32 / 64 / 128
    constexpr int STR = KP + 8;                 // padded k-stride (halfs; conflict-free frags)
    constexpr int NT = OUT / 32;                // n8-tiles per warp (4 for 128, 2 for 64)

    extern __shared__ __half smh[];
    __half* Ws = smh;                           // [OUT][STR]
    __half* As = smh + OUT * STR;               // [64][STR]
    float* Bs = (float*)(smh + OUT * STR + 64 * STR);

    int tid = threadIdx.x;
    int row0 = blockIdx.x * 64;

    // stage W transposed: Ws[col][k]
    for (int i = tid; i < IN * OUT; i += 256) {
        int k = i / OUT, col = i - k * OUT;
        Ws[col * STR + k] = __float2half_rn(W[i]);
    }
    if (KP > IN) {
        for (int i = tid; i < (KP - IN) * OUT; i += 256) {
            int col = i % OUT, k = IN + i / OUT;
            Ws[col * STR + k] = __ushort_as_half(0);
        }
    }
    for (int i = tid; i < OUT; i += 256) Bs[i] = bias ? bias[i] : 0.0f;

    // stage A tile (fp16 copy, no conversion)
    if (IN % 2 == 0) {
        constexpr int E2 = IN / 2;
        const uint32_t* A32 = (const uint32_t*)A;
        for (int i = tid; i < 64 * E2; i += 256) {
            int r = i / E2, kk = i - r * E2;
            int row = row0 + r;
            ((uint32_t*)(As + r * STR))[kk] =
                (row < n) ? A32[(size_t)row * E2 + kk] : 0u;
        }
    } else {
        for (int i = tid; i < 64 * IN; i += 256) {
            int r = i / IN, k = i - r * IN;
            int row = row0 + r;
            As[r * STR + k] = (row < n) ? A[(size_t)row * IN + k] : __ushort_as_half(0);
        }
    }
    if (KP > IN) {
        for (int i = tid; i < 64 * (KP - IN); i += 256) {
            int r = i / (KP - IN), k = IN + i % (KP - IN);
            As[r * STR + k] = __ushort_as_half(0);
        }
    }
    __syncthreads();

    int w = tid >> 5, lane = tid & 31;
    int wm = w >> 2, wn = w & 3;                // 2 x 4 warp grid: 32 rows x OUT/4 cols
    int g = lane >> 2, t4 = lane & 3;
    int rbase = wm * 32, cbase = wn * (OUT / 4);

    float acc[2][NT][4];
#pragma unroll
    for (int mt = 0; mt < 2; ++mt)
#pragma unroll
        for (int nt = 0; nt < NT; ++nt)
#pragma unroll
            for (int q = 0; q < 4; ++q) acc[mt][nt][q] = 0.0f;

#pragma unroll
    for (int k0 = 0; k0 < KP; k0 += 16) {
        uint32_t a[2][4];
#pragma unroll
        for (int mt = 0; mt < 2; ++mt) {
            int r = rbase + mt * 16 + g;
            a[mt][0] = *(const uint32_t*)(As + r * STR + k0 + 2 * t4);
            a[mt][1] = *(const uint32_t*)(As + (r + 8) * STR + k0 + 2 * t4);
            a[mt][2] = *(const uint32_t*)(As + r * STR + k0 + 2 * t4 + 8);
            a[mt][3] = *(const uint32_t*)(As + (r + 8) * STR + k0 + 2 * t4 + 8);
        }
        uint32_t b[NT][2];
#pragma unroll
        for (int nt = 0; nt < NT; ++nt) {
            int col = cbase + nt * 8 + g;
            b[nt][0] = *(const uint32_t*)(Ws + col * STR + k0 + 2 * t4);
            b[nt][1] = *(const uint32_t*)(Ws + col * STR + k0 + 2 * t4 + 8);
        }
#pragma unroll
        for (int mt = 0; mt < 2; ++mt)
#pragma unroll
            for (int nt = 0; nt < NT; ++nt) {
                asm volatile(
                    "mma.sync.aligned.m16n8k16.row.col.f32.f16.f16.f32 "
                    "{%0,%1,%2,%3}, {%4,%5,%6,%7}, {%8,%9}, {%0,%1,%2,%3};\n"
                    : "+f"(acc[mt][nt][0]), "+f"(acc[mt][nt][1]),
                      "+f"(acc[mt][nt][2]), "+f"(acc[mt][nt][3])
                    : "r"(a[mt][0]), "r"(a[mt][1]), "r"(a[mt][2]), "r"(a[mt][3]),
                      "r"(b[nt][0]), "r"(b[nt][1]));
            }
    }

    // epilogue: bias + optional relu -> fp16
#pragma unroll
    for (int mt = 0; mt < 2; ++mt) {
        int r1 = row0 + rbase + mt * 16 + g;
#pragma unroll
        for (int nt = 0; nt < NT; ++nt) {
            int col = cbase + nt * 8 + t4 * 2;
            float b0 = Bs[col], b1 = Bs[col + 1];
            if (r1 < n) {
                float v0 = acc[mt][nt][0] + b0;
                float v1 = acc[mt][nt][1] + b1;
                if (RELU) { v0 = fmaxf(v0, 0.0f); v1 = fmaxf(v1, 0.0f); }
                *(__half2*)(C + (size_t)r1 * OUT + col) = __floats2half2_rn(v0, v1);
            }
            if (r1 + 8 < n) {
                float v2 = acc[mt][nt][2] + b0;
                float v3 = acc[mt][nt][3] + b1;
                if (RELU) { v2 = fmaxf(v2, 0.0f); v3 = fmaxf(v3, 0.0f); }
                *(__half2*)(C + (size_t)(r1 + 8) * OUT + col) = __floats2half2_rn(v2, v3);
            }
        }
    }
}

// ---------------- host ----------------
template <int IN, int OUT, bool RELU>
static void launch_gemm_h(const __half* A, const float* W, const float* bias,
                          __half* C, int n) {
    constexpr int KP = ((IN + 15) / 16) * 16;
    constexpr int STR = KP + 8;
    size_t smb = (size_t)(OUT * STR + 64 * STR) * sizeof(__half) + OUT * sizeof(float);
    cudaFuncSetAttribute(gemm_h_k<IN, OUT, RELU>,
                         cudaFuncAttributeMaxDynamicSharedMemorySize, (int)smb);
    gemm_h_k<IN, OUT, RELU><<<(n + 63) / 64, 256, smb>>>(A, W, bias, C, n);
}

extern "C" void kernel_launch(void* const* d_in, const int* in_sizes, int n_in,
                              void* d_out, int out_size) {
    const float* x   = (const float*)d_in[0];
    const int*   ei  = (const int*)d_in[1];
    const int E = in_sizes[1] / 2;
    const int n = in_sizes[0] / 19;
    const int* src = ei;
    const int* dst = ei + E;

    const float* l0w1 = (const float*)d_in[2];
    const float* l0b1 = (const float*)d_in[3];
    const float* l0w2 = (const float*)d_in[4];
    const float* l0b2 = (const float*)d_in[5];
    const float* l1w1 = (const float*)d_in[6];
    const float* l1b1 = (const float*)d_in[7];
    const float* l1w2 = (const float*)d_in[8];
    const float* l1b2 = (const float*)d_in[9];
    const float* l2w1 = (const float*)d_in[10];
    const float* l2b1 = (const float*)d_in[11];
    const float* l2w2 = (const float*)d_in[12];
    const float* l2b2 = (const float*)d_in[13];
    const float* l3w1 = (const float*)d_in[14];
    const float* l3b1 = (const float*)d_in[15];
    const float* l3w2 = (const float*)d_in[16];
    const float* l3b2 = (const float*)d_in[17];
    const float* m_w  = (const float*)d_in[18];
    const float* m_b  = (const float*)d_in[19];
    const float* d_w1 = (const float*)d_in[20];
    const float* d_b1 = (const float*)d_in[21];
    const float* d_w2 = (const float*)d_in[22];
    const float* d_b2 = (const float*)d_in[23];

    void *pH, *pZ, *pT, *pX, *pVm, *pVd, *pSc, *pTd, *pRow, *pCnt, *pPart, *pBsum, *pEsrc;
    cudaGetSymbolAddress(&pH, g_h16);
    cudaGetSymbolAddress(&pZ, g_z16);
    cudaGetSymbolAddress(&pT, g_t16);
    cudaGetSymbolAddress(&pX, g_x16);
    cudaGetSymbolAddress(&pVm, g_vm);
    cudaGetSymbolAddress(&pVd, g_vd);
    cudaGetSymbolAddress(&pSc, g_sc);
    cudaGetSymbolAddress(&pTd, g_td);
    cudaGetSymbolAddress(&pRow, g_rowp);
    cudaGetSymbolAddress(&pCnt, g_cnt);
    cudaGetSymbolAddress(&pPart, g_part);
    cudaGetSymbolAddress(&pBsum, g_bsum);
    cudaGetSymbolAddress(&pEsrc, g_esrc);
    __half* h16 = (__half*)pH;
    __half* z16 = (__half*)pZ;
    __half* t16 = (__half*)pT;
    __half* x16 = (__half*)pX;
    float* vm = (float*)pVm;
    float* vd = (float*)pVd;
    float* sc = (float*)pSc;
    float* td = (float*)pTd;
    int* rowp = (int*)pRow;
    int* cnt  = (int*)pCnt;
    int* part = (int*)pPart;
    int* bsum = (int*)pBsum;
    int* esrc = (int*)pEsrc;

    float* out = (float*)d_out;

    const int TB = 256;
    const int edgeBlocks = (E + TB - 1) / TB;
    const int nodeBlocks = (n + TB - 1) / TB;
    const int warpBlocks = (n * 32 + TB - 1) / TB;  // warp per node
    const int nb = (n + 255) / 256;

    // ---- independent precomputes ----
    f2h_k<<<(n * 19 + 255) / 256, 256>>>(x, x16, n * 19);
    precomp_k<<<1, 64>>>(l3w2, l3b2, m_w, m_b, d_w1, vm, vd, sc);

    // ---- CSR build ----
    cudaMemsetAsync(cnt, 0, (size_t)n * sizeof(int));
    count_k<<<edgeBlocks, TB>>>(dst, cnt, E);
    block_scan_k<<<nb, 256>>>(cnt, part, bsum, n);
    scan_bsum_k<<<1, 256>>>(bsum, nb);
    finalize_rowp_k<<<nodeBlocks, TB>>>(part, bsum, rowp, n);
    cudaMemsetAsync(cnt, 0, (size_t)n * sizeof(int));
    fill_k<<<edgeBlocks, TB>>>(src, dst, rowp, cnt, esrc, E);

    // ---- layer 0 ----
    agg19h_k<<<warpBlocks, TB>>>(x16, rowp, esrc, z16, n);
    launch_gemm_h<19, 128, true>(z16, l0w1, l0b1, t16, n);
    launch_gemm_h<128, 128, true>(t16, l0w2, l0b2, h16, n);   // h0 fp16 (relu folded)

    // ---- layer 1 ----
    agg128h_k<<<warpBlocks, TB>>>(h16, rowp, esrc, z16, n);
    launch_gemm_h<128, 128, true>(z16, l1w1, l1b1, t16, n);
    launch_gemm_h<128, 128, true>(t16, l1w2, l1b2, h16, n);   // h1 fp16

    // ---- layer 2 ----
    agg128h_k<<<warpBlocks, TB>>>(h16, rowp, esrc, z16, n);
    launch_gemm_h<128, 128, true>(z16, l2w1, l2b1, t16, n);
    launch_gemm_h<128, 128, true>(t16, l2w2, l2b2, z16, n);   // h2 fp16 (into z16)

    // ---- layer 3: y = h2 @ W1 (64-dim fp16), aggregate at 64, fused heads ----
    launch_gemm_h<128, 64, false>(z16, l3w1, nullptr, h16, n); // y fp16
    agg64_heads_k<<<warpBlocks, TB>>>(h16, rowp, esrc, l3b1, vm, vd, sc,
                                      out + n, td, n);

    // ---- discriminator ----
    discrim_k<<<nodeBlocks, TB>>>(td, rowp, esrc, d_b1, d_w2, d_b2, out, n);
}

// round 8
// speedup vs baseline: 1.3473x; 1.1393x over previous
#include <cuda_runtime.h>
#include <cuda_fp16.h>
#include <cstdint>

#define NN 50000
#define NE 1600000

// ---------------- scratch (static device globals; no allocs allowed) ----------------
__device__ __half g_h16[NN * 128];   // gather source / y
__device__ __half g_z16[NN * 128];   // agg output / GEMM input
__device__ __half g_t16[NN * 128];   // MLP intermediate
__device__ __half g_x16[NN * 19];
__device__ float  g_vm[64];
__device__ float  g_vd[64];
__device__ float  g_sc[2];
__device__ float  g_td[NN];
__device__ int    g_rowp[NN + 1];
__device__ int    g_cnt[NN];
__device__ int    g_part[NN];
__device__ int    g_bsum[256];
__device__ int    g_esrc[NE];

// ---------------- CSR build ----------------
__global__ void count_k(const int* __restrict__ dst, int* __restrict__ cnt, int E) {
    int e = blockIdx.x * blockDim.x + threadIdx.x;
    if (e < E) atomicAdd(&cnt[dst[e]], 1);
}

__global__ void block_scan_k(const int* __restrict__ cnt, int* __restrict__ part,
                             int* __restrict__ bsum, int n) {
    __shared__ int wsum[8];
    int t = threadIdx.x;
    int i = blockIdx.x * 256 + t;
    int v = (i < n) ? cnt[i] : 0;
    int lane = t & 31, w = t >> 5;
    int x = v;
#pragma unroll
    for (int o = 1; o < 32; o <<= 1) {
        int y = __shfl_up_sync(0xffffffffu, x, o);
        if (lane >= o) x += y;
    }
    if (lane == 31) wsum[w] = x;
    __syncthreads();
    if (w == 0) {
        int s = (lane < 8) ? wsum[lane] : 0;
#pragma unroll
        for (int o = 1; o < 8; o <<= 1) {
            int y = __shfl_up_sync(0xffffffffu, s, o);
            if (lane >= o) s += y;
        }
        if (lane < 8) wsum[lane] = s;
    }
    __syncthreads();
    if (w > 0) x += wsum[w - 1];
    if (i < n) part[i] = x;
    if (t == 255) bsum[blockIdx.x] = x;
}

__global__ void scan_bsum_k(int* __restrict__ bsum, int nb) {
    __shared__ int wsum[8];
    int t = threadIdx.x;
    int v = (t < nb) ? bsum[t] : 0;
    int lane = t & 31, w = t >> 5;
    int x = v;
#pragma unroll
    for (int o = 1; o < 32; o <<= 1) {
        int y = __shfl_up_sync(0xffffffffu, x, o);
        if (lane >= o) x += y;
    }
    if (lane == 31) wsum[w] = x;
    __syncthreads();
    if (w == 0) {
        int s = (lane < 8) ? wsum[lane] : 0;
#pragma unroll
        for (int o = 1; o < 8; o <<= 1) {
            int y = __shfl_up_sync(0xffffffffu, s, o);
            if (lane >= o) s += y;
        }
        if (lane < 8) wsum[lane] = s;
    }
    __syncthreads();
    if (w > 0) x += wsum[w - 1];
    if (t < nb) bsum[t] = x - v;   // exclusive
}

__global__ void finalize_rowp_k(const int* __restrict__ part, const int* __restrict__ bsum,
                                int* __restrict__ rowp, int n) {
    int i = blockIdx.x * blockDim.x + threadIdx.x;
    if (i == 0) rowp[0] = 0;
    if (i < n) rowp[i + 1] = part[i] + bsum[i >> 8];
}

__global__ void fill_k(const int* __restrict__ src, const int* __restrict__ dst,
                       const int* __restrict__ rowp, int* __restrict__ cursor,
                       int* __restrict__ esrc, int E) {
    int e = blockIdx.x * blockDim.x + threadIdx.x;
    if (e >= E) return;
    int d = dst[e];
    int p = atomicAdd(&cursor[d], 1);
    esrc[rowp[d] + p] = src[e];
}

// ---------------- fp32 -> fp16 conversion ----------------
__global__ void f2h_k(const float* __restrict__ x, __half* __restrict__ xh, int n) {
    int i = blockIdx.x * blockDim.x + threadIdx.x;
    if (i < n) xh[i] = __float2half_rn(x[i]);
}

// ---------------- head precompute: v_m = W2@m_w, v_d = W2@d_w1 ----------------
__global__ void precomp_k(const float* __restrict__ W2, const float* __restrict__ b2,
                          const float* __restrict__ m_w, const float* __restrict__ m_b,
                          const float* __restrict__ d_w1,
                          float* __restrict__ vm, float* __restrict__ vd,
                          float* __restrict__ sc) {
    int i = threadIdx.x;  // 64 threads
    float am = 0.0f, ad = 0.0f;
    for (int k = 0; k < 64; ++k) {
        float w = W2[i * 64 + k];
        am += w * m_w[k];
        ad += w * d_w1[k];
    }
    vm[i] = am;
    vd[i] = ad;
    if (i == 0) {
        float sm = m_b[0], sd = 0.0f;
        for (int k = 0; k < 64; ++k) {
            sm += b2[k] * m_w[k];
            sd += b2[k] * d_w1[k];
        }
        sc[0] = sm;
        sc[1] = sd;
    }
}

// ---------------- aggregation kernels (warp per node; z = self + sum_{j->i}) ----------------
__global__ void agg19h_k(const __half* __restrict__ xh, const int* __restrict__ rowp,
                         const int* __restrict__ esrc, __half* __restrict__ z, int n) {
    int w = (blockIdx.x * blockDim.x + threadIdx.x) >> 5;
    int lane = threadIdx.x & 31;
    if (w >= n || lane >= 19) return;
    float acc = __half2float(xh[w * 19 + lane]);
    int s = rowp[w], e = rowp[w + 1];
    int j = s;
    for (; j + 4 <= e; j += 4) {
        int s0 = esrc[j], s1 = esrc[j + 1], s2 = esrc[j + 2], s3 = esrc[j + 3];
        float a = __half2float(xh[s0 * 19 + lane]);
        float b = __half2float(xh[s1 * 19 + lane]);
        float c = __half2float(xh[s2 * 19 + lane]);
        float d = __half2float(xh[s3 * 19 + lane]);
        acc += a; acc += b; acc += c; acc += d;
    }
    for (; j < e; ++j) acc += __half2float(xh[esrc[j] * 19 + lane]);
    z[w * 19 + lane] = __float2half_rn(acc);
}

__device__ __forceinline__ void acc_h4(float4& acc, uint2 v) {
    float2 f0 = __half22float2(*(__half2*)&v.x);
    float2 f1 = __half22float2(*(__half2*)&v.y);
    acc.x += f0.x; acc.y += f0.y; acc.z += f1.x; acc.w += f1.y;
}

// 128-dim fp16 gather -> fp16 z out. Each lane covers 4 features (uint2 = 8B). 8-deep MLP.
__global__ void agg128h_k(const __half* __restrict__ h, const int* __restrict__ rowp,
                          const int* __restrict__ esrc, __half* __restrict__ z, int n) {
    int w = (blockIdx.x * blockDim.x + threadIdx.x) >> 5;
    int lane = threadIdx.x & 31;
    if (w >= n) return;
    const uint2* h4 = (const uint2*)h;
    float4 acc = make_float4(0.f, 0.f, 0.f, 0.f);
    acc_h4(acc, h4[w * 32 + lane]);
    int s = rowp[w], e = rowp[w + 1];
    int j = s;
    for (; j + 8 <= e; j += 8) {
        int i0 = esrc[j],     i1 = esrc[j + 1], i2 = esrc[j + 2], i3 = esrc[j + 3];
        int i4 = esrc[j + 4], i5 = esrc[j + 5], i6 = esrc[j + 6], i7 = esrc[j + 7];
        uint2 v0 = h4[i0 * 32 + lane];
        uint2 v1 = h4[i1 * 32 + lane];
        uint2 v2 = h4[i2 * 32 + lane];
        uint2 v3 = h4[i3 * 32 + lane];
        uint2 v4 = h4[i4 * 32 + lane];
        uint2 v5 = h4[i5 * 32 + lane];
        uint2 v6 = h4[i6 * 32 + lane];
        uint2 v7 = h4[i7 * 32 + lane];
        acc_h4(acc, v0); acc_h4(acc, v1); acc_h4(acc, v2); acc_h4(acc, v3);
        acc_h4(acc, v4); acc_h4(acc, v5); acc_h4(acc, v6); acc_h4(acc, v7);
    }
    for (; j < e; ++j) acc_h4(acc, h4[esrc[j] * 32 + lane]);
    uint2 o;
    *(__half2*)&o.x = __floats2half2_rn(acc.x, acc.y);
    *(__half2*)&o.y = __floats2half2_rn(acc.z, acc.w);
    ((uint2*)z)[w * 32 + lane] = o;
}

// 64-dim fp16 gather + bias + ReLU + fused dual head dot products. 8-deep MLP.
__global__ void agg64_heads_k(const __half* __restrict__ y, const int* __restrict__ rowp,
                              const int* __restrict__ esrc, const float* __restrict__ bias,
                              const float* __restrict__ vm, const float* __restrict__ vd,
                              const float* __restrict__ sc,
                              float* __restrict__ mmse_out, float* __restrict__ td, int n) {
    int w = (blockIdx.x * blockDim.x + threadIdx.x) >> 5;
    int lane = threadIdx.x & 31;
    if (w >= n) return;
    const __half2* h2 = (const __half2*)y;  // 32 half2 per row
    float2 acc = __half22float2(h2[w * 32 + lane]);
    int s = rowp[w], e = rowp[w + 1];
    int j = s;
    for (; j + 8 <= e; j += 8) {
        int i0 = esrc[j],     i1 = esrc[j + 1], i2 = esrc[j + 2], i3 = esrc[j + 3];
        int i4 = esrc[j + 4], i5 = esrc[j + 5], i6 = esrc[j + 6], i7 = esrc[j + 7];
        float2 a = __half22float2(h2[i0 * 32 + lane]);
        float2 b = __half22float2(h2[i1 * 32 + lane]);
        float2 c = __half22float2(h2[i2 * 32 + lane]);
        float2 d = __half22float2(h2[i3 * 32 + lane]);
        float2 p = __half22float2(h2[i4 * 32 + lane]);
        float2 q = __half22float2(h2[i5 * 32 + lane]);
        float2 r = __half22float2(h2[i6 * 32 + lane]);
        float2 t = __half22float2(h2[i7 * 32 + lane]);
        acc.x += a.x; acc.y += a.y; acc.x += b.x; acc.y += b.y;
        acc.x += c.x; acc.y += c.y; acc.x += d.x; acc.y += d.y;
        acc.x += p.x; acc.y += p.y; acc.x += q.x; acc.y += q.y;
        acc.x += r.x; acc.y += r.y; acc.x += t.x; acc.y += t.y;
    }
    for (; j < e; ++j) {
        float2 f = __half22float2(h2[esrc[j] * 32 + lane]);
        acc.x += f.x; acc.y += f.y;
    }
    float ux = fmaxf(acc.x + bias[lane * 2], 0.0f);
    float uy = fmaxf(acc.y + bias[lane * 2 + 1], 0.0f);
    float dm = ux * vm[lane * 2] + uy * vm[lane * 2 + 1];
    float dd = ux * vd[lane * 2] + uy * vd[lane * 2 + 1];
#pragma unroll
    for (int o = 16; o; o >>= 1) {
        dm += __shfl_down_sync(0xffffffffu, dm, o);
        dd += __shfl_down_sync(0xffffffffu, dd, o);
    }
    if (lane == 0) {
        float m = dm + sc[0];
        mmse_out[w] = (m > 0.0f) ? m : 0.01f * m;
        td[w] = dd + sc[1];
    }
}

__global__ void discrim_k(const float* __restrict__ td, const int* __restrict__ rowp,
                          const int* __restrict__ esrc, const float* __restrict__ d_b1,
                          const float* __restrict__ d_w2, const float* __restrict__ d_b2,
                          float* __restrict__ out, int n) {
    int i = blockIdx.x * blockDim.x + threadIdx.x;
    if (i >= n) return;
    float acc = td[i];
    int s = rowp[i], e = rowp[i + 1];
    int j = s;
    for (; j + 4 <= e; j += 4) {
        float a = td[esrc[j]], b = td[esrc[j + 1]];
        float c = td[esrc[j + 2]], d = td[esrc[j + 3]];
        acc += a; acc += b; acc += c; acc += d;
    }
    for (; j < e; ++j) acc += td[esrc[j]];
    float u = acc + d_b1[0];
    u = fmaxf(u, 0.0f);
    out[i] = u * d_w2[0] + d_b2[0];
}

// ---------------- fp16 tensor-core GEMM (m16n8k16, ldmatrix, 128-row tiles) ----------------
__device__ __forceinline__ void ldsm4(uint32_t& r0, uint32_t& r1, uint32_t& r2, uint32_t& r3,
                                      uint32_t addr) {
    asm volatile("ldmatrix.sync.aligned.m8n8.x4.shared.b16 {%0,%1,%2,%3}, [%4];"
                 : "=r"(r0), "=r"(r1), "=r"(r2), "=r"(r3) : "r"(addr));
}

// C[n,OUT] = act(A[n,IN] @ W[IN,OUT] + bias); A fp16, W fp32->fp16, C fp16.
// Block 256 threads = 8 warps as 4m x 2n; tile 128 rows x OUT cols; K resident.
template <int IN, int OUT, bool RELU>
__global__ void gemm_h_k(const __half* __restrict__ A, const float* __restrict__ W,
                         const float* __restrict__ bias, __half* __restrict__ C, int n) {
    constexpr int KP = ((IN + 15) / 16) * 16;   // 32 / 128
    constexpr int STR = KP + 8;                 // padded k-stride in halfs
    constexpr int NT = OUT / 16;                // n8-tiles per warp (8 for 128, 4 for 64)

    extern __shared__ __half smh[];
    __half* Ws = smh;                           // [OUT][STR]
    __half* As = smh + OUT * STR;               // [128][STR]
    float* Bs = (float*)(smh + OUT * STR + 128 * STR);

    int tid = threadIdx.x;
    int row0 = blockIdx.x * 128;

    // stage W transposed: Ws[col][k]
    for (int i = tid; i < IN * OUT; i += 256) {
        int k = i / OUT, col = i - k * OUT;
        Ws[col * STR + k] = __float2half_rn(W[i]);
    }
    if (KP > IN) {
        for (int i = tid; i < (KP - IN) * OUT; i += 256) {
            int col = i % OUT, k = IN + i / OUT;
            Ws[col * STR + k] = __ushort_as_half(0);
        }
    }
    for (int i = tid; i < OUT; i += 256) Bs[i] = bias ? bias[i] : 0.0f;

    // stage A tile
    if (IN % 2 == 0) {
        constexpr int E2 = IN / 2;
        const uint32_t* A32 = (const uint32_t*)A;
        for (int i = tid; i < 128 * E2; i += 256) {
            int r = i / E2, kk = i - r * E2;
            int row = row0 + r;
            ((uint32_t*)(As + r * STR))[kk] = (row < n) ? A32[(size_t)row * E2 + kk] : 0u;
        }
    } else {
        for (int i = tid; i < 128 * IN; i += 256) {
            int r = i / IN, k = i - r * IN;
            int row = row0 + r;
            As[r * STR + k] = (row < n) ? A[(size_t)row * IN + k] : __ushort_as_half(0);
        }
    }
    if (KP > IN) {
        for (int i = tid; i < 128 * (KP - IN); i += 256) {
            int r = i / (KP - IN), k = IN + i % (KP - IN);
            As[r * STR + k] = __ushort_as_half(0);
        }
    }
    __syncthreads();

    int w = tid >> 5, lane = tid & 31;
    int wm = w >> 1, wn = w & 1;                // 4 x 2 warp grid
    int g = lane >> 2, t4 = lane & 3;
    int rbase = wm * 32, cbase = wn * (OUT / 2);

    int q = lane & 7, set = lane >> 3;          // ldmatrix lane roles
    // A: r0..r3 = a0..a3 -> row = rbase+mt*16+(set&1)*8+q, koff = (set>>1)*8
    uint32_t aA0 = (uint32_t)__cvta_generic_to_shared(
        As + (rbase + (set & 1) * 8 + q) * STR + (set >> 1) * 8);
    uint32_t aA1 = aA0 + 16 * STR * 2;
    // B (pair p covers nt=2p,2p+1): col = cbase+p*16+(set>>1)*8+q, koff = (set&1)*8
    uint32_t aB[NT / 2];
#pragma unroll
    for (int p = 0; p < NT / 2; ++p)
        aB[p] = (uint32_t)__cvta_generic_to_shared(
            Ws + (cbase + p * 16 + (set >> 1) * 8 + q) * STR + (set & 1) * 8);

    float acc[2][NT][4];
#pragma unroll
    for (int mt = 0; mt < 2; ++mt)
#pragma unroll
        for (int nt = 0; nt < NT; ++nt)
#pragma unroll
            for (int z = 0; z < 4; ++z) acc[mt][nt][z] = 0.0f;

#pragma unroll
    for (int k0 = 0; k0 < KP; k0 += 16) {
        uint32_t a[2][4];
        ldsm4(a[0][0], a[0][1], a[0][2], a[0][3], aA0 + k0 * 2);
        ldsm4(a[1][0], a[1][1], a[1][2], a[1][3], aA1 + k0 * 2);
        uint32_t b[NT][2];
#pragma unroll
        for (int p = 0; p < NT / 2; ++p) {
            uint32_t r0, r1, r2, r3;
            ldsm4(r0, r1, r2, r3, aB[p] + k0 * 2);
            b[2 * p][0] = r0; b[2 * p][1] = r1;
            b[2 * p + 1][0] = r2; b[2 * p + 1][1] = r3;
        }
#pragma unroll
        for (int mt = 0; mt < 2; ++mt)
#pragma unroll
            for (int nt = 0; nt < NT; ++nt) {
                asm volatile(
                    "mma.sync.aligned.m16n8k16.row.col.f32.f16.f16.f32 "
                    "{%0,%1,%2,%3}, {%4,%5,%6,%7}, {%8,%9}, {%0,%1,%2,%3};\n"
                    : "+f"(acc[mt][nt][0]), "+f"(acc[mt][nt][1]),
                      "+f"(acc[mt][nt][2]), "+f"(acc[mt][nt][3])
                    : "r"(a[mt][0]), "r"(a[mt][1]), "r"(a[mt][2]), "r"(a[mt][3]),
                      "r"(b[nt][0]), "r"(b[nt][1]));
            }
    }

    // epilogue: bias + optional relu -> fp16
#pragma unroll
    for (int mt = 0; mt < 2; ++mt) {
        int r1 = row0 + rbase + mt * 16 + g;
#pragma unroll
        for (int nt = 0; nt < NT; ++nt) {
            int col = cbase + nt * 8 + t4 * 2;
            float b0 = Bs[col], b1 = Bs[col + 1];
            if (r1 < n) {
                float v0 = acc[mt][nt][0] + b0;
                float v1 = acc[mt][nt][1] + b1;
                if (RELU) { v0 = fmaxf(v0, 0.0f); v1 = fmaxf(v1, 0.0f); }
                *(__half2*)(C + (size_t)r1 * OUT + col) = __floats2half2_rn(v0, v1);
            }
            if (r1 + 8 < n) {
                float v2 = acc[mt][nt][2] + b0;
                float v3 = acc[mt][nt][3] + b1;
                if (RELU) { v2 = fmaxf(v2, 0.0f); v3 = fmaxf(v3, 0.0f); }
                *(__half2*)(C + (size_t)(r1 + 8) * OUT + col) = __floats2half2_rn(v2, v3);
            }
        }
    }
}

// ---------------- host ----------------
template <int IN, int OUT, bool RELU>
static void launch_gemm_h(const __half* A, const float* W, const float* bias,
                          __half* C, int n) {
    constexpr int KP = ((IN + 15) / 16) * 16;
    constexpr int STR = KP + 8;
    size_t smb = (size_t)(OUT * STR + 128 * STR) * sizeof(__half) + OUT * sizeof(float);
    cudaFuncSetAttribute(gemm_h_k<IN, OUT, RELU>,
                         cudaFuncAttributeMaxDynamicSharedMemorySize, (int)smb);
    gemm_h_k<IN, OUT, RELU><<<(n + 127) / 128, 256, smb>>>(A, W, bias, C, n);
}

extern "C" void kernel_launch(void* const* d_in, const int* in_sizes, int n_in,
                              void* d_out, int out_size) {
    const float* x   = (const float*)d_in[0];
    const int*   ei  = (const int*)d_in[1];
    const int E = in_sizes[1] / 2;
    const int n = in_sizes[0] / 19;
    const int* src = ei;
    const int* dst = ei + E;

    const float* l0w1 = (const float*)d_in[2];
    const float* l0b1 = (const float*)d_in[3];
    const float* l0w2 = (const float*)d_in[4];
    const float* l0b2 = (const float*)d_in[5];
    const float* l1w1 = (const float*)d_in[6];
    const float* l1b1 = (const float*)d_in[7];
    const float* l1w2 = (const float*)d_in[8];
    const float* l1b2 = (const float*)d_in[9];
    const float* l2w1 = (const float*)d_in[10];
    const float* l2b1 = (const float*)d_in[11];
    const float* l2w2 = (const float*)d_in[12];
    const float* l2b2 = (const float*)d_in[13];
    const float* l3w1 = (const float*)d_in[14];
    const float* l3b1 = (const float*)d_in[15];
    const float* l3w2 = (const float*)d_in[16];
    const float* l3b2 = (const float*)d_in[17];
    const float* m_w  = (const float*)d_in[18];
    const float* m_b  = (const float*)d_in[19];
    const float* d_w1 = (const float*)d_in[20];
    const float* d_b1 = (const float*)d_in[21];
    const float* d_w2 = (const float*)d_in[22];
    const float* d_b2 = (const float*)d_in[23];

    void *pH, *pZ, *pT, *pX, *pVm, *pVd, *pSc, *pTd, *pRow, *pCnt, *pPart, *pBsum, *pEsrc;
    cudaGetSymbolAddress(&pH, g_h16);
    cudaGetSymbolAddress(&pZ, g_z16);
    cudaGetSymbolAddress(&pT, g_t16);
    cudaGetSymbolAddress(&pX, g_x16);
    cudaGetSymbolAddress(&pVm, g_vm);
    cudaGetSymbolAddress(&pVd, g_vd);
    cudaGetSymbolAddress(&pSc, g_sc);
    cudaGetSymbolAddress(&pTd, g_td);
    cudaGetSymbolAddress(&pRow, g_rowp);
    cudaGetSymbolAddress(&pCnt, g_cnt);
    cudaGetSymbolAddress(&pPart, g_part);
    cudaGetSymbolAddress(&pBsum, g_bsum);
    cudaGetSymbolAddress(&pEsrc, g_esrc);
    __half* h16 = (__half*)pH;
    __half* z16 = (__half*)pZ;
    __half* t16 = (__half*)pT;
    __half* x16 = (__half*)pX;
    float* vm = (float*)pVm;
    float* vd = (float*)pVd;
    float* sc = (float*)pSc;
    float* td = (float*)pTd;
    int* rowp = (int*)pRow;
    int* cnt  = (int*)pCnt;
    int* part = (int*)pPart;
    int* bsum = (int*)pBsum;
    int* esrc = (int*)pEsrc;

    float* out = (float*)d_out;

    const int TB = 256;
    const int edgeBlocks = (E + TB - 1) / TB;
    const int nodeBlocks = (n + TB - 1) / TB;
    const int warpBlocks = (n * 32 + TB - 1) / TB;  // warp per node
    const int nb = (n + 255) / 256;

    // ---- independent precomputes ----
    f2h_k<<<(n * 19 + 255) / 256, 256>>>(x, x16, n * 19);
    precomp_k<<<1, 64>>>(l3w2, l3b2, m_w, m_b, d_w1, vm, vd, sc);

    // ---- CSR build ----
    cudaMemsetAsync(cnt, 0, (size_t)n * sizeof(int));
    count_k<<<edgeBlocks, TB>>>(dst, cnt, E);
    block_scan_k<<<nb, 256>>>(cnt, part, bsum, n);
    scan_bsum_k<<<1, 256>>>(bsum, nb);
    finalize_rowp_k<<<nodeBlocks, TB>>>(part, bsum, rowp, n);
    cudaMemsetAsync(cnt, 0, (size_t)n * sizeof(int));
    fill_k<<<edgeBlocks, TB>>>(src, dst, rowp, cnt, esrc, E);

    // ---- layer 0 ----
    agg19h_k<<<warpBlocks, TB>>>(x16, rowp, esrc, z16, n);
    launch_gemm_h<19, 128, true>(z16, l0w1, l0b1, t16, n);
    launch_gemm_h<128, 128, true>(t16, l0w2, l0b2, h16, n);   // h0 fp16 (relu folded)

    // ---- layer 1 ----
    agg128h_k<<<warpBlocks, TB>>>(h16, rowp, esrc, z16, n);
    launch_gemm_h<128, 128, true>(z16, l1w1, l1b1, t16, n);
    launch_gemm_h<128, 128, true>(t16, l1w2, l1b2, h16, n);   // h1 fp16

    // ---- layer 2 ----
    agg128h_k<<<warpBlocks, TB>>>(h16, rowp, esrc, z16, n);
    launch_gemm_h<128, 128, true>(z16, l2w1, l2b1, t16, n);
    launch_gemm_h<128, 128, true>(t16, l2w2, l2b2, z16, n);   // h2 fp16 (into z16)

    // ---- layer 3: y = h2 @ W1 (64-dim fp16), aggregate at 64, fused heads ----
    launch_gemm_h<128, 64, false>(z16, l3w1, nullptr, h16, n); // y fp16
    agg64_heads_k<<<warpBlocks, TB>>>(h16, rowp, esrc, l3b1, vm, vd, sc,
                                      out + n, td, n);

    // ---- discriminator ----
    discrim_k<<<nodeBlocks, TB>>>(td, rowp, esrc, d_b1, d_w2, d_b2, out, n);
}